// round 8
// baseline (speedup 1.0000x reference)
#include <cuda_runtime.h>
#include <math.h>

// LundWeight reweighting, round 8: single-pass scan, predicated STS (no dump
// slot, no BSSY), coalesced strided group loads, one atomic per 8-element half.
// z (8192,128,25) f32; mT (8192,128) f32; observable (8192,2) i32 (mult=[:,0]).
// Output (8192,) f32.

#define LOG2E 1.4426950408889634f
#define F2MIN (-72.13475f)  /* -50 * LOG2E */
#define OSF   15.0f

__device__ __forceinline__ float rcp_fast(float x){ float r; asm("rcp.approx.f32 %0,%1;":"=f"(r):"f"(x)); return r; }
__device__ __forceinline__ float lg2_fast(float x){ float r; asm("lg2.approx.f32 %0,%1;":"=f"(r):"f"(x)); return r; }
__device__ __forceinline__ float ex2_fast(float x){ float r; asm("ex2.approx.f32 %0,%1;":"=f"(r):"f"(x)); return r; }

__device__ __forceinline__ float zmax_calc(float a, float b) {
    const float c = 1.0f;
    if (a < 0.02f) return (c > b) ? b : 1.0f;
    if (fabsf(a - c) < 0.01f) return b / (b + c);
    float z = 0.5f * (b + c - sqrtf((b - c) * (b - c) + 4.0f * a * b)) / (c - a);
    if (z > 0.9999f && b > 100.0f) z = fminf(z, 1.0f - a / b);
    return z;
}

// Predicated shared store of {z, idx}: no branch, no wavefront when z == 0.
__device__ __forceinline__ void sts_pred(unsigned addr, float z, int idx) {
    asm volatile(
        "{ .reg .pred p; setp.ne.f32 p, %1, 0F00000000;\n\t"
        "  @p st.shared.v2.f32 [%0], {%1, %2}; }\n"
        :: "r"(addr), "f"(z), "f"(__int_as_float(idx)) : "memory");
}

__global__ __launch_bounds__(256, 7) void lund_weight_kernel(
    const float4* __restrict__ Z4,     // (B,800) float4 view of (B,128,25)
    const float*  __restrict__ MT,     // (B,128)
    const int*    __restrict__ OBS,    // (B,2) int32, [:,0] = mult
    const float*  __restrict__ p_a,
    const float*  __restrict__ p_b,
    const float*  __restrict__ p_base,
    float* __restrict__ out)           // (B,)
{
    __shared__ float4 sK[128];      // {be2P, C2P, be20, C20} per m (log2 domain)
    __shared__ float2 sZM[3200];    // compacted {z, idx bits}
    __shared__ int    sCnt;
    __shared__ float  sRed[8];

    const int b    = blockIdx.x;
    const int tid  = threadIdx.x;
    const int lane = tid & 31;
    if (tid == 0) sCnt = 0;

    const float aP = p_a[0],    bP = p_b[0];
    const float a0 = p_base[0], b0 = p_base[1];
    const float aUP = (aP < 0.02f) ? 0.0f : aP;
    const float aU0 = (a0 < 0.02f) ? 0.0f : a0;

    const int mult = OBS[b * 2];             // 20..128

    // ---- Phase 1: 2 param-sets x 128 m; log2-domain constants:
    //      f2 = C2 - be2/z - lg2 z + aU*lg2(1-z);  be2 = b_exp*LOG2E;
    //      C2 = be2/zmax + lg2 zmax - aU*lg2(1-zmax).
    {
        const int   set  = tid >> 7;
        const int   m    = tid & 127;
        const float a    = set ? a0  : aP;
        const float bpar = set ? b0  : bP;
        const float aU   = set ? aU0 : aUP;
        const float mt   = MT[b * 128 + m];
        const float be   = bpar * mt * mt;
        const float zm   = zmax_calc(a, be);
        const float be2  = be * LOG2E;
        float C2 = be2 * rcp_fast(zm) + lg2_fast(zm);
        if (aU != 0.0f) C2 -= aU * lg2_fast(1.0f - zm);
        float* sKf = (float*)sK;
        sKf[(m << 2) + (set << 1) + 0] = be2;
        sKf[(m << 2) + (set << 1) + 1] = C2;
    }
    __syncthreads();

    // ---- Phase 2: single-pass compaction of the valid region (first mult*25
    //      floats; rest of the row is exactly zero, quad over-read is inert).
    //      Two halves of 8 elements; groups strided by 256 quads => coalesced. ----
    const float4* __restrict__ zr = Z4 + (size_t)b * 800;
    const int nq = (mult * 25 + 3) >> 2;     // quads in valid region (<= 800)
    const unsigned sZMb = (unsigned)__cvta_generic_to_shared(sZM);

    #pragma unroll
    for (int h = 0; h < 2; ++h) {
        if ((h << 9) >= nq) break;           // uniform across block
        const int qa = tid + (h << 9);       // group A quad
        const int qb = qa + 256;             // group B quad
        float4 va = make_float4(0.f,0.f,0.f,0.f);
        float4 vb = make_float4(0.f,0.f,0.f,0.f);
        if (qa < nq) va = zr[qa];
        if (qb < nq) vb = zr[qb];

        const float e[8] = {va.x, va.y, va.z, va.w, vb.x, vb.y, vb.z, vb.w};
        int c = 0;
        #pragma unroll
        for (int j = 0; j < 8; ++j) c += (e[j] != 0.f);

        int pos = atomicAdd(&sCnt, c);
        const int ia = qa << 2, ib = qb << 2;
        #pragma unroll
        for (int j = 0; j < 8; ++j) {
            const int idx = (j < 4) ? (ia + j) : (ib + j - 4);
            sts_pred(sZMb + (unsigned)pos * 8u, e[j], idx);
            pos += (e[j] != 0.f);
        }
    }
    __syncthreads();
    const int n = sCnt;

    // ---- Phase 3: dense math over active elements ----
    float prod = 1.0f;
    #pragma unroll 1
    for (int i = tid; i < n; i += 256) {
        const float2 p   = sZM[i];
        const int    idx = __float_as_int(p.y);
        const int    m   = (idx * 5243) >> 17;   // exact idx/25 for idx<3200
        const bool   rej = (idx - m * 25) != 0;
        const float4 kk  = sK[m];
        const float  z   = p.x;

        const float rz  = rcp_fast(z);
        const float l2z = lg2_fast(z);
        const float l2o = lg2_fast(1.0f - z);

        float fP = fmaf(-kk.x, rz, kk.y);
        fP = fmaf(aUP, l2o, fP - l2z);
        float f0 = fmaf(-kk.z, rz, kk.w);
        f0 = fmaf(aU0, l2o, f0 - l2z);
        fP = fmaxf(fP, F2MIN);                // f <= 0 by construction
        f0 = fmaxf(f0, F2MIN);
        const float eP = ex2_fast(fP);
        const float e0 = ex2_fast(f0);

        const float num = rej ? (OSF - eP) : eP;
        const float den = rej ? (OSF - e0) : e0;
        prod *= num * rcp_fast(den);
    }

    // ---- Phase 4: block product reduction ----
    #pragma unroll
    for (int off = 16; off; off >>= 1)
        prod *= __shfl_xor_sync(0xffffffffu, prod, off);
    if (lane == 0) sRed[tid >> 5] = prod;
    __syncthreads();
    if (tid < 32) {
        float pr = (tid < 8) ? sRed[tid] : 1.0f;
        #pragma unroll
        for (int off = 4; off; off >>= 1)
            pr *= __shfl_xor_sync(0xffffffffu, pr, off);
        if (tid == 0) out[b] = pr;
    }
}

extern "C" void kernel_launch(void* const* d_in, const int* in_sizes, int n_in,
                              void* d_out, int out_size) {
    const float4* Z4     = (const float4*)d_in[0];
    const float*  MT     = (const float*)d_in[1];
    const int*    OBS    = (const int*)d_in[2];   // int32 on device
    const float*  p_a    = (const float*)d_in[3];
    const float*  p_b    = (const float*)d_in[4];
    const float*  p_base = (const float*)d_in[5];
    float* out = (float*)d_out;

    const int B = out_size;   // 8192
    lund_weight_kernel<<<B, 256>>>(Z4, MT, OBS, p_a, p_b, p_base, out);
}